// round 12
// baseline (speedup 1.0000x reference)
#include <cuda_runtime.h>
#include <cuda_bf16.h>
#include <cstdint>

// Weighted keypoint MSE loss:
//   oob = target outside [0,1024]^2; weight = oob ? 0.01 : 1.0
//   loss = sum_bk( weight * ||output-target||^2 ) / 4096
//
// R12 = R11 (per-warp self-paced TMA rings, 7 warps x 4 stages x 2KB/array,
// 2 CTAs/SM) but with CONTIGUOUS-SPAN chunk assignment: each warp streams
// sequentially through its own ~1.7MB slice of both arrays for DRAM row
// locality, instead of 4MB-strided round-robin.

#define HEIGHT_F 1024.0f
#define WIDTH_F  1024.0f
#define OOB_W    0.01f
#define B_DIM    4096.0

#define NBLOCKS     296          // 148 SMs * 2 CTAs
#define NWARPS      7
#define NTHREADS    (NWARPS * 32)   // 224
#define NSTAGES     4
#define CHUNK_F4    128          // float4 per chunk per array per warp (2KB)
#define CHUNK_BYTES (CHUNK_F4 * 16)
#define STAGE_F4    (2 * CHUNK_F4)                       // o + t
#define SMEM_BYTES  (NWARPS * NSTAGES * STAGE_F4 * 16)   // 112KB per CTA

__device__ double g_partials[NBLOCKS];
__device__ unsigned int g_count;   // zero-init; atomicInc self-wraps -> replay-safe

__device__ __forceinline__ uint32_t smem_u32(const void* p) {
    return (uint32_t)__cvta_generic_to_shared(p);
}

__device__ __forceinline__ void mbar_init(uint32_t mbar, uint32_t count) {
    asm volatile("mbarrier.init.shared.b64 [%0], %1;" :: "r"(mbar), "r"(count) : "memory");
}

__device__ __forceinline__ void mbar_expect_tx(uint32_t mbar, uint32_t bytes) {
    asm volatile("mbarrier.arrive.expect_tx.shared.b64 _, [%0], %1;"
                 :: "r"(mbar), "r"(bytes) : "memory");
}

__device__ __forceinline__ void mbar_wait(uint32_t mbar, uint32_t parity) {
    uint32_t done;
    asm volatile(
        "{\n\t.reg .pred p;\n\t"
        "mbarrier.try_wait.parity.acquire.cta.shared::cta.b64 p, [%1], %2;\n\t"
        "selp.b32 %0, 1, 0, p;\n\t}"
        : "=r"(done) : "r"(mbar), "r"(parity) : "memory");
    if (!done) {
        asm volatile(
            "{\n\t.reg .pred P1;\n\t"
            "WAIT_LOOP_%=:\n\t"
            "mbarrier.try_wait.parity.acquire.cta.shared::cta.b64 P1, [%0], %1, 0x989680;\n\t"
            "@P1 bra.uni WAIT_DONE_%=;\n\t"
            "bra.uni WAIT_LOOP_%=;\n\t"
            "WAIT_DONE_%=:\n\t}"
            :: "r"(mbar), "r"(parity) : "memory");
    }
}

__device__ __forceinline__ void bulk_g2s(uint32_t dst_smem, const void* src_gmem,
                                         uint32_t bytes, uint32_t mbar) {
    asm volatile(
        "cp.async.bulk.shared::cta.global.mbarrier::complete_tx::bytes [%0], [%1], %2, [%3];"
        :: "r"(dst_smem), "l"(src_gmem), "r"(bytes), "r"(mbar) : "memory");
}

__device__ __forceinline__ float pair_loss(float4 o, float4 t) {
    float dx0 = o.x - t.x;
    float dy0 = o.y - t.y;
    float sq0 = fmaf(dx0, dx0, dy0 * dy0);
    bool oob0 = (t.x < 0.0f) | (t.x > WIDTH_F) | (t.y < 0.0f) | (t.y > HEIGHT_F);
    float w0 = oob0 ? OOB_W : 1.0f;

    float dx1 = o.z - t.z;
    float dy1 = o.w - t.w;
    float sq1 = fmaf(dx1, dx1, dy1 * dy1);
    bool oob1 = (t.z < 0.0f) | (t.z > WIDTH_F) | (t.w < 0.0f) | (t.w > HEIGHT_F);
    float w1 = oob1 ? OOB_W : 1.0f;

    return fmaf(w0, sq0, w1 * sq1);
}

__device__ __forceinline__ double block_reduce(double v, double* warp_sums) {
    #pragma unroll
    for (int off = 16; off > 0; off >>= 1)
        v += __shfl_down_sync(0xFFFFFFFFu, v, off);
    int lane = threadIdx.x & 31;
    int wid  = threadIdx.x >> 5;
    if (lane == 0) warp_sums[wid] = v;
    __syncthreads();
    if (wid == 0) {
        v = (lane < NWARPS) ? warp_sums[lane] : 0.0;
        #pragma unroll
        for (int off = 4; off > 0; off >>= 1)
            v += __shfl_down_sync(0xFFFFFFFFu, v, off);
    }
    return v;  // valid in thread 0
}

__global__ __launch_bounds__(NTHREADS) void loss_kernel(
    const float4* __restrict__ outp,
    const float4* __restrict__ tgt,
    int n4,
    float* __restrict__ out)
{
    extern __shared__ __align__(16) float4 ring[];  // [NWARPS][NSTAGES][STAGE_F4]

    __shared__ __align__(8) unsigned long long mb[NWARPS][NSTAGES];
    __shared__ double warp_sums[NWARPS];
    __shared__ bool is_last;

    const int tid  = threadIdx.x;
    const int wid  = tid >> 5;
    const int lane = tid & 31;
    const int bid  = blockIdx.x;

    const int gw      = bid * NWARPS + wid;      // global warp id
    const int gwcount = NBLOCKS * NWARPS;        // 2072
    const int chunks_total = n4 / CHUNK_F4;      // 65536 for this shape

    // contiguous span for this warp: [c_lo, c_hi)
    const int c_lo = (int)(((long long)gw     * chunks_total) / gwcount);
    const int c_hi = (int)(((long long)(gw+1) * chunks_total) / gwcount);

    if (tid < NWARPS * NSTAGES)
        mbar_init(smem_u32(&mb[tid / NSTAGES][tid % NSTAGES]), 1);
    __syncthreads();

    float4* myring = ring + wid * (NSTAGES * STAGE_F4);

    // ---- prologue: lane 0 fills this warp's ring with its first chunks ----
    if (lane == 0) {
        #pragma unroll
        for (int p = 0; p < NSTAGES; p++) {
            int c = c_lo + p;
            if (c < c_hi) {
                uint32_t m = smem_u32(&mb[wid][p]);
                mbar_expect_tx(m, 2 * CHUNK_BYTES);
                float4* s = myring + p * STAGE_F4;
                bulk_g2s(smem_u32(s), outp + (size_t)c * CHUNK_F4, CHUNK_BYTES, m);
                bulk_g2s(smem_u32(s + CHUNK_F4), tgt + (size_t)c * CHUNK_F4, CHUNK_BYTES, m);
            }
        }
    }

    double acc = 0.0;

    // ---- self-paced main loop: sequential span, no cross-warp sync ----
    int stage = 0, phase = 0;
    for (int c = c_lo; c < c_hi; c++) {
        uint32_t m = smem_u32(&mb[wid][stage]);
        mbar_wait(m, phase);

        const float4* s_o = myring + stage * STAGE_F4 + lane;
        const float4* s_t = s_o + CHUNK_F4;
        float sum = 0.0f;
        #pragma unroll
        for (int j = 0; j < CHUNK_F4 / 32; j++) {     // 4 f4 per lane per array
            float4 o = s_o[32 * j];
            float4 t = s_t[32 * j];
            sum += pair_loss(o, t);
        }
        acc += (double)sum;

        __syncwarp();   // all lanes consumed this stage
        if (lane == 0) {
            int cn = c + NSTAGES;
            if (cn < c_hi) {
                mbar_expect_tx(m, 2 * CHUNK_BYTES);
                float4* d = myring + stage * STAGE_F4;
                bulk_g2s(smem_u32(d), outp + (size_t)cn * CHUNK_F4, CHUNK_BYTES, m);
                bulk_g2s(smem_u32(d + CHUNK_F4), tgt + (size_t)cn * CHUNK_F4, CHUNK_BYTES, m);
            }
        }

        if (++stage == NSTAGES) { stage = 0; phase ^= 1; }
    }

    // ---- tail (n4 not multiple of CHUNK_F4; empty for this shape) ----
    if (bid == 0) {
        for (int i = chunks_total * CHUNK_F4 + tid; i < n4; i += NTHREADS) {
            float4 o = __ldcs(outp + i);
            float4 t = __ldcs(tgt + i);
            acc += (double)pair_loss(o, t);
        }
    }

    // ---- reduce + last-block finalize ----
    double bsum = block_reduce(acc, warp_sums);

    if (tid == 0) {
        g_partials[bid] = bsum;
        __threadfence();
        unsigned int old = atomicInc(&g_count, NBLOCKS - 1);  // wraps to 0
        is_last = (old == NBLOCKS - 1);
    }
    __syncthreads();

    if (is_last) {
        __threadfence();
        double v = 0.0;
        for (int j = tid; j < NBLOCKS; j += NTHREADS)
            v += g_partials[j];
        __syncthreads();
        double total = block_reduce(v, warp_sums);
        if (tid == 0)
            out[0] = (float)(total / B_DIM);
    }
}

extern "C" void kernel_launch(void* const* d_in, const int* in_sizes, int n_in,
                              void* d_out, int out_size) {
    const float4* outp = (const float4*)d_in[0];
    const float4* tgt  = (const float4*)d_in[1];
    int n4 = in_sizes[0] / 4;   // float4 count (2 keypoints each)

    cudaFuncSetAttribute(loss_kernel,
                         cudaFuncAttributeMaxDynamicSharedMemorySize, SMEM_BYTES);

    loss_kernel<<<NBLOCKS, NTHREADS, SMEM_BYTES>>>(outp, tgt, n4, (float*)d_out);
}

// round 13
// speedup vs baseline: 1.0336x; 1.0336x over previous
#include <cuda_runtime.h>
#include <cuda_bf16.h>
#include <cstdint>

// Weighted keypoint MSE loss:
//   oob = target outside [0,1024]^2; weight = oob ? 0.01 : 1.0
//   loss = sum_bk( weight * ||output-target||^2 ) / 4096
//
// FINAL (= R11, best measured: kernel 45.8us, 5.94 TB/s, DRAM 75%):
// per-warp self-paced TMA pipelines, round-robin chunk assignment.
// 7 warps x 4-stage private rings x 2KB/array/stage = 112KB/CTA, 2 CTAs/SM
// (224KB/SM in flight). Lane 0 of each warp issues its own cp.async.bulk
// reloads; zero cross-warp sync in the hot loop. grid = 148*2 = one wave.
// Round-robin interleave beat contiguous spans (R12: -2.2%) — L2-hash
// load-balance favors many fine-grained interleaved streams.

#define HEIGHT_F 1024.0f
#define WIDTH_F  1024.0f
#define OOB_W    0.01f
#define B_DIM    4096.0

#define NBLOCKS     296          // 148 SMs * 2 CTAs
#define NWARPS      7
#define NTHREADS    (NWARPS * 32)   // 224
#define NSTAGES     4
#define CHUNK_F4    128          // float4 per chunk per array per warp (2KB)
#define CHUNK_BYTES (CHUNK_F4 * 16)
#define STAGE_F4    (2 * CHUNK_F4)                       // o + t
#define SMEM_BYTES  (NWARPS * NSTAGES * STAGE_F4 * 16)   // 112KB per CTA

__device__ double g_partials[NBLOCKS];
__device__ unsigned int g_count;   // zero-init; atomicInc self-wraps -> replay-safe

__device__ __forceinline__ uint32_t smem_u32(const void* p) {
    return (uint32_t)__cvta_generic_to_shared(p);
}

__device__ __forceinline__ void mbar_init(uint32_t mbar, uint32_t count) {
    asm volatile("mbarrier.init.shared.b64 [%0], %1;" :: "r"(mbar), "r"(count) : "memory");
}

__device__ __forceinline__ void mbar_expect_tx(uint32_t mbar, uint32_t bytes) {
    asm volatile("mbarrier.arrive.expect_tx.shared.b64 _, [%0], %1;"
                 :: "r"(mbar), "r"(bytes) : "memory");
}

__device__ __forceinline__ void mbar_wait(uint32_t mbar, uint32_t parity) {
    uint32_t done;
    asm volatile(
        "{\n\t.reg .pred p;\n\t"
        "mbarrier.try_wait.parity.acquire.cta.shared::cta.b64 p, [%1], %2;\n\t"
        "selp.b32 %0, 1, 0, p;\n\t}"
        : "=r"(done) : "r"(mbar), "r"(parity) : "memory");
    if (!done) {
        asm volatile(
            "{\n\t.reg .pred P1;\n\t"
            "WAIT_LOOP_%=:\n\t"
            "mbarrier.try_wait.parity.acquire.cta.shared::cta.b64 P1, [%0], %1, 0x989680;\n\t"
            "@P1 bra.uni WAIT_DONE_%=;\n\t"
            "bra.uni WAIT_LOOP_%=;\n\t"
            "WAIT_DONE_%=:\n\t}"
            :: "r"(mbar), "r"(parity) : "memory");
    }
}

__device__ __forceinline__ void bulk_g2s(uint32_t dst_smem, const void* src_gmem,
                                         uint32_t bytes, uint32_t mbar) {
    asm volatile(
        "cp.async.bulk.shared::cta.global.mbarrier::complete_tx::bytes [%0], [%1], %2, [%3];"
        :: "r"(dst_smem), "l"(src_gmem), "r"(bytes), "r"(mbar) : "memory");
}

__device__ __forceinline__ float pair_loss(float4 o, float4 t) {
    float dx0 = o.x - t.x;
    float dy0 = o.y - t.y;
    float sq0 = fmaf(dx0, dx0, dy0 * dy0);
    bool oob0 = (t.x < 0.0f) | (t.x > WIDTH_F) | (t.y < 0.0f) | (t.y > HEIGHT_F);
    float w0 = oob0 ? OOB_W : 1.0f;

    float dx1 = o.z - t.z;
    float dy1 = o.w - t.w;
    float sq1 = fmaf(dx1, dx1, dy1 * dy1);
    bool oob1 = (t.z < 0.0f) | (t.z > WIDTH_F) | (t.w < 0.0f) | (t.w > HEIGHT_F);
    float w1 = oob1 ? OOB_W : 1.0f;

    return fmaf(w0, sq0, w1 * sq1);
}

__device__ __forceinline__ double block_reduce(double v, double* warp_sums) {
    #pragma unroll
    for (int off = 16; off > 0; off >>= 1)
        v += __shfl_down_sync(0xFFFFFFFFu, v, off);
    int lane = threadIdx.x & 31;
    int wid  = threadIdx.x >> 5;
    if (lane == 0) warp_sums[wid] = v;
    __syncthreads();
    if (wid == 0) {
        v = (lane < NWARPS) ? warp_sums[lane] : 0.0;
        #pragma unroll
        for (int off = 4; off > 0; off >>= 1)
            v += __shfl_down_sync(0xFFFFFFFFu, v, off);
    }
    return v;  // valid in thread 0
}

__global__ __launch_bounds__(NTHREADS) void loss_kernel(
    const float4* __restrict__ outp,
    const float4* __restrict__ tgt,
    int n4,
    float* __restrict__ out)
{
    extern __shared__ __align__(16) float4 ring[];  // [NWARPS][NSTAGES][STAGE_F4]

    __shared__ __align__(8) unsigned long long mb[NWARPS][NSTAGES];
    __shared__ double warp_sums[NWARPS];
    __shared__ bool is_last;

    const int tid  = threadIdx.x;
    const int wid  = tid >> 5;
    const int lane = tid & 31;
    const int bid  = blockIdx.x;

    const int gw      = bid * NWARPS + wid;      // global warp id
    const int gwcount = NBLOCKS * NWARPS;        // 2072
    const int chunks_total = n4 / CHUNK_F4;      // 65536 for this shape

    if (tid < NWARPS * NSTAGES)
        mbar_init(smem_u32(&mb[tid / NSTAGES][tid % NSTAGES]), 1);
    __syncthreads();

    float4* myring = ring + wid * (NSTAGES * STAGE_F4);

    // ---- prologue: lane 0 fills this warp's ring ----
    if (lane == 0) {
        #pragma unroll
        for (int p = 0; p < NSTAGES; p++) {
            int c = gw + p * gwcount;
            if (c < chunks_total) {
                uint32_t m = smem_u32(&mb[wid][p]);
                mbar_expect_tx(m, 2 * CHUNK_BYTES);
                float4* s = myring + p * STAGE_F4;
                bulk_g2s(smem_u32(s), outp + (size_t)c * CHUNK_F4, CHUNK_BYTES, m);
                bulk_g2s(smem_u32(s + CHUNK_F4), tgt + (size_t)c * CHUNK_F4, CHUNK_BYTES, m);
            }
        }
    }

    double acc = 0.0;

    // ---- self-paced main loop (no cross-warp sync) ----
    int stage = 0, phase = 0;
    for (int c = gw; c < chunks_total; c += gwcount) {
        uint32_t m = smem_u32(&mb[wid][stage]);
        mbar_wait(m, phase);

        const float4* s_o = myring + stage * STAGE_F4 + lane;
        const float4* s_t = s_o + CHUNK_F4;
        float sum = 0.0f;
        #pragma unroll
        for (int j = 0; j < CHUNK_F4 / 32; j++) {     // 4 f4 per lane per array
            float4 o = s_o[32 * j];
            float4 t = s_t[32 * j];
            sum += pair_loss(o, t);
        }
        acc += (double)sum;

        __syncwarp();   // all lanes consumed this stage
        if (lane == 0) {
            int cn = c + NSTAGES * gwcount;
            if (cn < chunks_total) {
                mbar_expect_tx(m, 2 * CHUNK_BYTES);
                float4* d = myring + stage * STAGE_F4;
                bulk_g2s(smem_u32(d), outp + (size_t)cn * CHUNK_F4, CHUNK_BYTES, m);
                bulk_g2s(smem_u32(d + CHUNK_F4), tgt + (size_t)cn * CHUNK_F4, CHUNK_BYTES, m);
            }
        }

        if (++stage == NSTAGES) { stage = 0; phase ^= 1; }
    }

    // ---- tail (n4 not multiple of CHUNK_F4; empty for this shape) ----
    if (bid == 0) {
        for (int i = chunks_total * CHUNK_F4 + tid; i < n4; i += NTHREADS) {
            float4 o = __ldcs(outp + i);
            float4 t = __ldcs(tgt + i);
            acc += (double)pair_loss(o, t);
        }
    }

    // ---- reduce + last-block finalize ----
    double bsum = block_reduce(acc, warp_sums);

    if (tid == 0) {
        g_partials[bid] = bsum;
        __threadfence();
        unsigned int old = atomicInc(&g_count, NBLOCKS - 1);  // wraps to 0
        is_last = (old == NBLOCKS - 1);
    }
    __syncthreads();

    if (is_last) {
        __threadfence();
        double v = 0.0;
        for (int j = tid; j < NBLOCKS; j += NTHREADS)
            v += g_partials[j];
        __syncthreads();
        double total = block_reduce(v, warp_sums);
        if (tid == 0)
            out[0] = (float)(total / B_DIM);
    }
}

extern "C" void kernel_launch(void* const* d_in, const int* in_sizes, int n_in,
                              void* d_out, int out_size) {
    const float4* outp = (const float4*)d_in[0];
    const float4* tgt  = (const float4*)d_in[1];
    int n4 = in_sizes[0] / 4;   // float4 count (2 keypoints each)

    cudaFuncSetAttribute(loss_kernel,
                         cudaFuncAttributeMaxDynamicSharedMemorySize, SMEM_BYTES);

    loss_kernel<<<NBLOCKS, NTHREADS, SMEM_BYTES>>>(outp, tgt, n4, (float*)d_out);
}